// round 1
// baseline (speedup 1.0000x reference)
#include <cuda_runtime.h>
#include <math.h>

// Problem constants
#define PD 64      // number of splits
#define KD 64      // samples per side per split
#define ND 128     // 2*KD points per split
#define DD 2048    // feature dim
#define NCH 4      // D-chunks for gram_kernel parallelism
#define DCH 512    // DD / NCH

// Scratch (static device globals: no allocation allowed in kernel_launch)
__device__ float g_part[NCH][PD][ND][ND];  // partial grams, 16 MB
__device__ float g_sums[PD][4];            // per-split quadrant sums (xx, xy, yx, yy)
__device__ float g_l2max[PD];              // per-split max l2

// ---------------------------------------------------------------------------
// Kernel 1: partial Gram. blockIdx.x = D-chunk, blockIdx.y = split.
// 256 threads, each computes an 8x8 block of the 128x128 Gram over 512 dims.
// Smem tile is transposed [dim][point] so operand reads are contiguous float4s.
// ---------------------------------------------------------------------------
__global__ void __launch_bounds__(256) gram_kernel(const float* __restrict__ src,
                                                   const float* __restrict__ tgt) {
    const int c = blockIdx.x;
    const int p = blockIdx.y;
    const int t = threadIdx.x;
    const int tx = t & 15;   // j-block
    const int ty = t >> 4;   // i-block

    __shared__ float T[32][132];   // 132-float stride: 16B-aligned rows, keeps float4 reads legal

    float acc[8][8];
#pragma unroll
    for (int ii = 0; ii < 8; ii++)
#pragma unroll
        for (int jj = 0; jj < 8; jj++) acc[ii][jj] = 0.f;

    // Loader mapping: thread loads one float4 for 4 points (pt, pt+32, pt+64, pt+96)
    const int ld_pt = t >> 3;            // 0..31
    const int ld_d  = (t & 7) << 2;      // 0,4,...,28
    const float* rowp[4];
#pragma unroll
    for (int r = 0; r < 4; r++) {
        int pt = ld_pt + 32 * r;
        const float* base = (pt < KD) ? (src + (size_t)(p * KD + pt) * DD)
                                      : (tgt + (size_t)(p * KD + (pt - KD)) * DD);
        rowp[r] = base + c * DCH + ld_d;
    }

    for (int k = 0; k < DCH / 32; k++) {
        float4 v[4];
#pragma unroll
        for (int r = 0; r < 4; r++)
            v[r] = *(const float4*)(rowp[r] + k * 32);

        __syncthreads();   // protect reads of previous tile
#pragma unroll
        for (int r = 0; r < 4; r++) {
            int pt = ld_pt + 32 * r;
            T[ld_d + 0][pt] = v[r].x;
            T[ld_d + 1][pt] = v[r].y;
            T[ld_d + 2][pt] = v[r].z;
            T[ld_d + 3][pt] = v[r].w;
        }
        __syncthreads();

#pragma unroll 4
        for (int d = 0; d < 32; d++) {
            float4 a0 = *(const float4*)&T[d][ty * 8];
            float4 a1 = *(const float4*)&T[d][ty * 8 + 4];
            float4 b0 = *(const float4*)&T[d][tx * 8];
            float4 b1 = *(const float4*)&T[d][tx * 8 + 4];
            float av[8] = {a0.x, a0.y, a0.z, a0.w, a1.x, a1.y, a1.z, a1.w};
            float bv[8] = {b0.x, b0.y, b0.z, b0.w, b1.x, b1.y, b1.z, b1.w};
#pragma unroll
            for (int ii = 0; ii < 8; ii++)
#pragma unroll
                for (int jj = 0; jj < 8; jj++)
                    acc[ii][jj] = fmaf(av[ii], bv[jj], acc[ii][jj]);
        }
    }

    float* outp = &g_part[c][p][0][0];
#pragma unroll
    for (int ii = 0; ii < 8; ii++)
#pragma unroll
        for (int jj = 0; jj < 8; jj++)
            outp[(ty * 8 + ii) * ND + (tx * 8 + jj)] = acc[ii][jj];
}

// ---------------------------------------------------------------------------
// Kernel 2: per split — l2, bandwidth, 5-kernel RBF sums per quadrant, max l2.
// One CTA per split, 256 threads: thread t handles row i = t/2, half-row of
// 64 cols at jb = (t&1)*64. All reductions done by thread 0 in a fixed order
// (deterministic, no float atomics).
// ---------------------------------------------------------------------------
__global__ void __launch_bounds__(256) mmd_kernel() {
    const int p = blockIdx.x;
    const int t = threadIdx.x;
    const int i = t >> 1;
    const int jb = (t & 1) << 6;

    __shared__ float diag[ND];
    __shared__ float red[256];
    __shared__ float s_bw;

    // Diagonal of the full gram (sum of the 4 partials)
    if (t < ND) {
        float g = 0.f;
#pragma unroll
        for (int c = 0; c < NCH; c++) g += g_part[c][p][t][t];
        diag[t] = g;
    }
    __syncthreads();

    const float di = diag[i];

    // Pass 1: sum(l2) and max(l2)
    float lsum = 0.f, lmax = 0.f;
    for (int jj = 0; jj < 64; jj++) {
        int j = jb + jj;
        float g = 0.f;
#pragma unroll
        for (int c = 0; c < NCH; c++) g += g_part[c][p][i][j];
        float l2 = di + diag[j] - 2.f * g;
        lsum += l2;
        lmax = fmaxf(lmax, l2);
    }

    red[t] = lsum;
    __syncthreads();
    if (t == 0) {
        float s = 0.f;
        for (int k = 0; k < 256; k++) s += red[k];
        // bw = sum(l2)/(n^2-n) / KERNEL_MUL^(KERNEL_NUM/2) = sum/16256/4
        s_bw = s / (float)(ND * ND - ND) * 0.25f;
    }
    __syncthreads();
    red[t] = lmax;
    __syncthreads();
    if (t == 0) {
        float m = 0.f;
        for (int k = 0; k < 256; k++) m = fmaxf(m, red[k]);
        g_l2max[p] = m;
    }

    // Bandwidths: bws[m] = bw * 2^m + 1e-9
    const float bw = s_bw;
    float inv[5];
#pragma unroll
    for (int m = 0; m < 5; m++) {
        float bwm = bw * (float)(1 << m) + 1e-9f;
        inv[m] = 1.f / bwm;
    }

    // Pass 2: sum over 5 RBF kernels (recompute l2 from gram partials)
    float qsum = 0.f;
    for (int jj = 0; jj < 64; jj++) {
        int j = jb + jj;
        float g = 0.f;
#pragma unroll
        for (int c = 0; c < NCH; c++) g += g_part[c][p][i][j];
        float l2 = di + diag[j] - 2.f * g;
        float kv = 0.f;
#pragma unroll
        for (int m = 0; m < 5; m++) kv += expf(-l2 * inv[m]);
        qsum += kv;
    }

    __syncthreads();
    red[t] = qsum;
    __syncthreads();
    if (t == 0) {
        // quadrant: 0 = XX (i<64,j<64), 1 = XY, 2 = YX, 3 = YY
        float q[4] = {0.f, 0.f, 0.f, 0.f};
        for (int k = 0; k < 256; k++) {
            int ik = k >> 1;
            int quad = ((ik >= KD) ? 2 : 0) + (k & 1);
            q[quad] += red[k];
        }
        g_sums[p][0] = q[0];
        g_sums[p][1] = q[1];
        g_sums[p][2] = q[2];
        g_sums[p][3] = q[3];
    }
}

// ---------------------------------------------------------------------------
// Kernel 3: fixed-order final reduction across splits -> 6 output scalars.
// ---------------------------------------------------------------------------
__global__ void finalize_kernel(float* __restrict__ out) {
    float X = 0.f, Y = 0.f, XY = 0.f, YX = 0.f;
    for (int p = 0; p < PD; p++) {
        X  += g_sums[p][0] * (1.f / 4096.f);
        XY += g_sums[p][1] * (1.f / 4096.f);
        YX += g_sums[p][2] * (1.f / 4096.f);
        Y  += g_sums[p][3] * (1.f / 4096.f);
    }
    out[0] = (X + Y - XY - YX) * (1.f / 64.f);  // total_loss
    out[1] = g_l2max[PD - 1];                   // max(l2[-1])
    out[2] = X * (1.f / 64.f);                  // sum(xx)/P
    out[3] = Y * (1.f / 64.f);                  // sum(yy)/P
    out[4] = XY * (1.f / 64.f);                 // sum(xy)/P
    out[5] = YX * (1.f / 64.f);                 // sum(yx)/P
}

extern "C" void kernel_launch(void* const* d_in, const int* in_sizes, int n_in,
                              void* d_out, int out_size) {
    const float* src = (const float*)d_in[0];
    const float* tgt = (const float*)d_in[1];

    dim3 g1(NCH, PD);
    gram_kernel<<<g1, 256>>>(src, tgt);
    mmd_kernel<<<PD, 256>>>();
    finalize_kernel<<<1, 1>>>((float*)d_out);
}

// round 3
// speedup vs baseline: 4.7627x; 4.7627x over previous
#include <cuda_runtime.h>
#include <cuda_bf16.h>
#include <stdint.h>

// Problem constants
#define PD 64      // splits
#define KD 64      // samples per side
#define ND 128     // points per split
#define DD 2048    // feature dim
#define NCH 2      // D halves -> 128 CTAs for the gram stage
#define KC (DD / NCH)     // 1024 K per CTA
#define NCHK (KC / 64)    // 16 chunks of 64 K

// Scratch (device globals; no allocation allowed)
__device__ float g_part[NCH][PD][ND][ND];  // partial grams, 8 MB (L2-resident)
__device__ float g_sums[PD][4];            // xx, xy, yx, yy per split
__device__ float g_l2max[PD];

__device__ __forceinline__ uint32_t smem_u32(const void* p) {
    uint32_t a;
    asm("{ .reg .u64 t; cvta.to.shared.u64 t, %1; cvt.u32.u64 %0, t; }"
        : "=r"(a) : "l"(p));
    return a;
}

__device__ __forceinline__ void ldsm_x4(uint32_t& r0, uint32_t& r1, uint32_t& r2,
                                        uint32_t& r3, uint32_t addr) {
    asm volatile("ldmatrix.sync.aligned.m8n8.x4.shared.b16 {%0,%1,%2,%3}, [%4];"
                 : "=r"(r0), "=r"(r1), "=r"(r2), "=r"(r3) : "r"(addr));
}

__device__ __forceinline__ void mma_bf16(float* c, const uint32_t* a, const uint32_t* b) {
    asm volatile(
        "mma.sync.aligned.m16n8k16.row.col.f32.bf16.bf16.f32 "
        "{%0,%1,%2,%3}, {%4,%5,%6,%7}, {%8,%9}, {%0,%1,%2,%3};"
        : "+f"(c[0]), "+f"(c[1]), "+f"(c[2]), "+f"(c[3])
        : "r"(a[0]), "r"(a[1]), "r"(a[2]), "r"(a[3]), "r"(b[0]), "r"(b[1]));
}

// ---------------------------------------------------------------------------
// Kernel 1: partial Gram via HMMA. blockIdx.x = D-half, blockIdx.y = split.
// 256 threads = 8 warps; warp tile 32x64 of the 128x128 output.
// SMEM: double-buffered 128 x 64 bf16 tiles, rows padded to 72 (144 bytes).
// ---------------------------------------------------------------------------
__global__ void __launch_bounds__(256) gram_kernel(const float* __restrict__ src,
                                                   const float* __restrict__ tgt) {
    const int nc = blockIdx.x;
    const int p  = blockIdx.y;
    const int t  = threadIdx.x;
    const int lane = t & 31;
    const int w    = t >> 5;

    __shared__ __align__(16) __nv_bfloat16 tile[2][ND][72];

    // ---- loader mapping: thread t loads 8 rows (rb + 16s), one float4 each ----
    const int f4 = t & 15;          // float4 column 0..15 (covers 64 floats)
    const int rb = t >> 4;          // base row 0..15
    const float* rowp[8];
#pragma unroll
    for (int s = 0; s < 8; s++) {
        int r = rb + 16 * s;
        const float* base = (r < KD) ? (src + (size_t)(p * KD + r) * DD)
                                     : (tgt + (size_t)(p * KD + (r - KD)) * DD);
        rowp[s] = base + nc * KC + f4 * 4;
    }
    char* tbase[2] = { (char*)&tile[0][0][0], (char*)&tile[1][0][0] };
    uint32_t sts[8];
#pragma unroll
    for (int s = 0; s < 8; s++)
        sts[s] = (uint32_t)((rb + 16 * s) * 144 + f4 * 8);

    // ---- mma mapping: warp tile at (wm, wn) ----
    const int wm = (w & 3) << 5;    // 0,32,64,96
    const int wn = (w >> 2) << 6;   // 0,64
    uint32_t tb[2] = { smem_u32(tbase[0]), smem_u32(tbase[1]) };
    uint32_t aaddr[2][2], baddr[2][4];
#pragma unroll
    for (int b = 0; b < 2; b++) {
#pragma unroll
        for (int mi = 0; mi < 2; mi++)
            aaddr[b][mi] = tb[b] + (uint32_t)((wm + mi * 16 + (lane & 15)) * 144
                                              + (lane >> 4) * 16);
#pragma unroll
        for (int nj = 0; nj < 4; nj++)
            baddr[b][nj] = tb[b] + (uint32_t)((wn + nj * 16 + ((lane >> 4) << 3)
                                               + (lane & 7)) * 144
                                              + ((lane >> 3) & 1) * 16);
    }

    float acc[2][8][4];
#pragma unroll
    for (int mi = 0; mi < 2; mi++)
#pragma unroll
        for (int nj = 0; nj < 8; nj++)
#pragma unroll
            for (int r = 0; r < 4; r++) acc[mi][nj][r] = 0.f;

    float4 v[8];
    // prologue: load chunk 0, stage it
#pragma unroll
    for (int s = 0; s < 8; s++) v[s] = *(const float4*)(rowp[s]);
#pragma unroll
    for (int s = 0; s < 8; s++) {
        __nv_bfloat162 lo = __floats2bfloat162_rn(v[s].x, v[s].y);
        __nv_bfloat162 hi = __floats2bfloat162_rn(v[s].z, v[s].w);
        uint2 u = { *(uint32_t*)&lo, *(uint32_t*)&hi };
        *(uint2*)(tbase[0] + sts[s]) = u;
    }
    __syncthreads();

    for (int ch = 0; ch < NCHK; ch++) {
        if (ch + 1 < NCHK) {
#pragma unroll
            for (int s = 0; s < 8; s++)
                v[s] = *(const float4*)(rowp[s] + (ch + 1) * 64);
        }
        const int b = ch & 1;
#pragma unroll
        for (int k16 = 0; k16 < 4; k16++) {
            uint32_t a[2][4], bb[8][2];
            ldsm_x4(a[0][0], a[0][1], a[0][2], a[0][3], aaddr[b][0] + k16 * 32);
            ldsm_x4(a[1][0], a[1][1], a[1][2], a[1][3], aaddr[b][1] + k16 * 32);
#pragma unroll
            for (int nj = 0; nj < 4; nj++)
                ldsm_x4(bb[2 * nj][0], bb[2 * nj][1], bb[2 * nj + 1][0],
                        bb[2 * nj + 1][1], baddr[b][nj] + k16 * 32);
#pragma unroll
            for (int mi = 0; mi < 2; mi++)
#pragma unroll
                for (int nj = 0; nj < 8; nj++)
                    mma_bf16(acc[mi][nj], a[mi], bb[nj]);
        }
        if (ch + 1 < NCHK) {
            char* dst = tbase[(ch + 1) & 1];
#pragma unroll
            for (int s = 0; s < 8; s++) {
                __nv_bfloat162 lo = __floats2bfloat162_rn(v[s].x, v[s].y);
                __nv_bfloat162 hi = __floats2bfloat162_rn(v[s].z, v[s].w);
                uint2 u = { *(uint32_t*)&lo, *(uint32_t*)&hi };
                *(uint2*)(dst + sts[s]) = u;
            }
            __syncthreads();
        }
    }

    // write accumulators: lane l owns rows (l>>2, l>>2+8), cols (l&3)*2 (+1)
    float* outp = &g_part[nc][p][0][0];
    const int rr = lane >> 2;
    const int cc = (lane & 3) * 2;
#pragma unroll
    for (int mi = 0; mi < 2; mi++)
#pragma unroll
        for (int nj = 0; nj < 8; nj++) {
            int row = wm + mi * 16 + rr;
            int col = wn + nj * 8 + cc;
            *(float2*)&outp[row * ND + col] =
                make_float2(acc[mi][nj][0], acc[mi][nj][1]);
            *(float2*)&outp[(row + 8) * ND + col] =
                make_float2(acc[mi][nj][2], acc[mi][nj][3]);
        }
}

// ---------------------------------------------------------------------------
// Kernel 2: per-split MMD epilogue. One CTA per split, 256 threads.
// Thread layout: quadrant q = t>>6 (bit1 = i-half, bit0 = j-half),
// u = t&63 -> row i = (q>>1)*64 + u, cols jb = (q&1)*64 .. +63.
// Row-half kept in registers across both passes. Tree reductions (fixed order).
// ---------------------------------------------------------------------------
__global__ void __launch_bounds__(256) mmd_kernel() {
    const int p = blockIdx.x;
    const int t = threadIdx.x;
    const int q = t >> 6;
    const int u = t & 63;
    const int i = ((q >> 1) << 6) + u;
    const int jb = (q & 1) << 6;

    __shared__ float diag[ND];
    __shared__ float red[256], red2[256];
    __shared__ float s_bw;

    const float* p0 = &g_part[0][p][0][0];
    const float* p1 = &g_part[1][p][0][0];

    float g[64];
#pragma unroll
    for (int j4 = 0; j4 < 16; j4++) {
        float4 A = *(const float4*)&p0[i * ND + jb + j4 * 4];
        float4 B = *(const float4*)&p1[i * ND + jb + j4 * 4];
        g[4 * j4 + 0] = A.x + B.x;
        g[4 * j4 + 1] = A.y + B.y;
        g[4 * j4 + 2] = A.z + B.z;
        g[4 * j4 + 3] = A.w + B.w;
    }
    if (t < ND) diag[t] = p0[t * ND + t] + p1[t * ND + t];
    __syncthreads();

    const float di = diag[i];

    // Pass 1: sum(l2), max(l2)
    float lsum = 0.f, lmax = 0.f;
#pragma unroll
    for (int jj = 0; jj < 64; jj++) {
        float l2 = di + diag[jb + jj] - 2.f * g[jj];
        lsum += l2;
        lmax = fmaxf(lmax, l2);
    }
    red[t] = lsum;
    red2[t] = lmax;
    __syncthreads();
#pragma unroll
    for (int s = 128; s > 0; s >>= 1) {
        if (t < s) {
            red[t] += red[t + s];
            red2[t] = fmaxf(red2[t], red2[t + s]);
        }
        __syncthreads();
    }
    if (t == 0) {
        s_bw = red[0] / (float)(ND * ND - ND) * 0.25f;  // /(n^2-n)/2^(5/2)
        g_l2max[p] = red2[0];
    }
    __syncthreads();

    const float bw = s_bw;
    float inv[5];
#pragma unroll
    for (int m = 0; m < 5; m++)
        inv[m] = 1.f / (bw * (float)(1 << m) + 1e-9f);

    // Pass 2: 5-RBF kernel sum for this row-half
    float qs = 0.f;
#pragma unroll
    for (int jj = 0; jj < 64; jj++) {
        float l2 = di + diag[jb + jj] - 2.f * g[jj];
        float kv = 0.f;
#pragma unroll
        for (int m = 0; m < 5; m++)
            kv += __expf(-l2 * inv[m]);
        qs += kv;
    }
    red[t] = qs;
    __syncthreads();
#pragma unroll
    for (int s = 32; s > 0; s >>= 1) {
        if (u < s) red[t] += red[t + s];
        __syncthreads();
    }
    if (u == 0) g_sums[p][q] = red[t];   // q: 0=xx, 1=xy, 2=yx, 3=yy
}

// ---------------------------------------------------------------------------
// Kernel 3: fixed-order final reduction across splits -> 6 output scalars.
// ---------------------------------------------------------------------------
__global__ void finalize_kernel(float* __restrict__ out) {
    float X = 0.f, Y = 0.f, XY = 0.f, YX = 0.f;
    for (int p = 0; p < PD; p++) {
        X  += g_sums[p][0] * (1.f / 4096.f);
        XY += g_sums[p][1] * (1.f / 4096.f);
        YX += g_sums[p][2] * (1.f / 4096.f);
        Y  += g_sums[p][3] * (1.f / 4096.f);
    }
    out[0] = (X + Y - XY - YX) * (1.f / 64.f);  // total_loss
    out[1] = g_l2max[PD - 1];                   // max(l2[-1])
    out[2] = X * (1.f / 64.f);                  // sum(xx)/P
    out[3] = Y * (1.f / 64.f);                  // sum(yy)/P
    out[4] = XY * (1.f / 64.f);                 // sum(xy)/P
    out[5] = YX * (1.f / 64.f);                 // sum(yx)/P
}

extern "C" void kernel_launch(void* const* d_in, const int* in_sizes, int n_in,
                              void* d_out, int out_size) {
    const float* src = (const float*)d_in[0];
    const float* tgt = (const float*)d_in[1];

    dim3 g1(NCH, PD);
    gram_kernel<<<g1, 256>>>(src, tgt);
    mmd_kernel<<<PD, 256>>>();
    finalize_kernel<<<1, 1>>>((float*)d_out);
}